// round 4
// baseline (speedup 1.0000x reference)
#include <cuda_runtime.h>
#include <cstdint>

// Problem constants (from reference):
//   B=256, P=4096, H=W=512
// Inputs (metadata order):
//   d_in[0]: indices   int32  [B, P, 2]   (JAX x64 disabled: jnp.int64 request -> int32)
//   d_in[1]: num_valid int32  [B]
//   d_in[2]: feats     float32[B, P, 1]
// Output: float32 [B, H, W]

#define B_ 256
#define P_ 4096
#define H_ 512
#define W_ 512

#define SPLIT_ 4                      // sub-CTAs per batch (row quarters)
#define ROWS_PER_ (H_ / SPLIT_)       // 128 rows per sub-CTA
#define THREADS_ 256

__global__ __launch_bounds__(THREADS_, 8)
void scatter_densify_split_kernel(const int* __restrict__ indices,
                                  const int* __restrict__ num_valid,
                                  const float* __restrict__ feats,
                                  float* __restrict__ out)
{
    const int bid = blockIdx.x;
    const int b   = bid >> 2;          // batch
    const int q   = bid & 3;           // row quarter
    const int r0  = q * ROWS_PER_;     // first row owned by this CTA

    float* slice = out + (size_t)b * (H_ * W_);     // batch slice base
    float* qbase = slice + (size_t)r0 * W_;         // this CTA's quarter

    // Hoist scalar load; latency hides under the fill loop.
    const int nv = num_valid[b];

    // ---- Phase 1: zero this CTA's 128x512 quarter (256 KB) ----
    // 128*512 floats = 16384 float4; 256 threads -> 64 iterations.
    float4* s4 = reinterpret_cast<float4*>(qbase);
    const float4 z = make_float4(0.f, 0.f, 0.f, 0.f);
    const int n4 = (ROWS_PER_ * W_) / 4;
    #pragma unroll 8
    for (int i = threadIdx.x; i < n4; i += THREADS_) {
        s4[i] = z;
    }
    __syncthreads();

    // ---- Phase 2: scan ALL valid points of batch b, keep rows in [r0, r0+128) ----
    const int2*  ib = reinterpret_cast<const int2*>(indices) + (size_t)b * P_;
    const float* fb = feats + (size_t)b * P_;

    for (int p = threadIdx.x; p < nv; p += THREADS_) {
        int2 rc = ib[p];
        int r = rc.x - r0;                       // row relative to quarter
        int c = rc.y;
        if ((unsigned)r < ROWS_PER_ && (unsigned)c < W_) {
            atomicAdd(qbase + r * W_ + c, fb[p]);
        }
    }
}

extern "C" void kernel_launch(void* const* d_in, const int* in_sizes, int n_in,
                              void* d_out, int out_size)
{
    const int*   indices = (const int*)d_in[0];
    const int*   nvalid  = (const int*)d_in[1];
    const float* feats   = (const float*)d_in[2];
    float*       out     = (float*)d_out;

    scatter_densify_split_kernel<<<B_ * SPLIT_, THREADS_>>>(indices, nvalid, feats, out);
}

// round 5
// speedup vs baseline: 1.2058x; 1.2058x over previous
#include <cuda_runtime.h>
#include <cstdint>

// Problem constants (from reference):
//   B=256, P=4096, H=W=512
// Inputs (metadata order):
//   d_in[0]: indices   int32  [B, P, 2]   (JAX x64 disabled: jnp.int64 request -> int32)
//   d_in[1]: num_valid int32  [B]
//   d_in[2]: feats     float32[B, P, 1]
// Output: float32 [B, H, W]

#define B_ 256
#define P_ 4096
#define H_ 512
#define W_ 512

#define THREADS_    1024
#define SMEM_BYTES  32768                       // 32 KB zero buffer (static smem <= 48 KB)
#define SLICE_BYTES (H_ * W_ * 4)               // 1 MB per batch
#define N_CHUNKS    (SLICE_BYTES / SMEM_BYTES)  // 32 bulk stores per batch

__device__ __forceinline__ uint32_t smem_u32(const void* p) {
    uint32_t a;
    asm("{ .reg .u64 t; cvta.to.shared.u64 t, %1; cvt.u32.u64 %0, t; }"
        : "=r"(a) : "l"(p));
    return a;
}

__global__ __launch_bounds__(THREADS_, 1)
void scatter_densify_tma_kernel(const int* __restrict__ indices,
                                const int* __restrict__ num_valid,
                                const float* __restrict__ feats,
                                float* __restrict__ out)
{
    __shared__ __align__(128) float4 zbuf[SMEM_BYTES / 16];

    const int b = blockIdx.x;
    float* slice = out + (size_t)b * (H_ * W_);
    const int nv = num_valid[b];   // hoisted; latency hidden under smem zeroing

    // ---- Phase 1a: zero the 32 KB SMEM staging buffer (2 iterations) ----
    const float4 z = make_float4(0.f, 0.f, 0.f, 0.f);
    #pragma unroll
    for (int i = threadIdx.x; i < SMEM_BYTES / 16; i += THREADS_) {
        zbuf[i] = z;
    }
    __syncthreads();

    // ---- Phase 1b: TMA bulk-store the zeros over this batch's 1 MB slice ----
    // Async-proxy writes bypass the per-thread L1tex store path entirely.
    if (threadIdx.x == 0) {
        asm volatile("fence.proxy.async.shared::cta;" ::: "memory");
        const uint32_t src = smem_u32(zbuf);
        char* dst = reinterpret_cast<char*>(slice);
        #pragma unroll
        for (int c = 0; c < N_CHUNKS; c++) {
            asm volatile(
                "cp.async.bulk.global.shared::cta.bulk_group [%0], [%1], %2;"
                :: "l"(dst + (size_t)c * SMEM_BYTES), "r"(src), "n"(SMEM_BYTES)
                : "memory");
        }
        asm volatile("cp.async.bulk.commit_group;" ::: "memory");
        asm volatile("cp.async.bulk.wait_group 0;" ::: "memory");
    }
    __syncthreads();   // all threads see completed zero-fill

    // ---- Phase 2: scatter-add valid points (4 iterations) ----
    const int2*  ib = reinterpret_cast<const int2*>(indices) + (size_t)b * P_;
    const float* fb = feats + (size_t)b * P_;

    for (int p = threadIdx.x; p < nv; p += THREADS_) {
        int2 rc = ib[p];
        int r = rc.x;
        int c = rc.y;
        if ((unsigned)r < H_ && (unsigned)c < W_) {
            atomicAdd(slice + r * W_ + c, fb[p]);
        }
    }
}

extern "C" void kernel_launch(void* const* d_in, const int* in_sizes, int n_in,
                              void* d_out, int out_size)
{
    const int*   indices = (const int*)d_in[0];
    const int*   nvalid  = (const int*)d_in[1];
    const float* feats   = (const float*)d_in[2];
    float*       out     = (float*)d_out;

    scatter_densify_tma_kernel<<<B_, THREADS_>>>(indices, nvalid, feats, out);
}